// round 14
// baseline (speedup 1.0000x reference)
#include <cuda_runtime.h>
#include <cuda_fp16.h>
#include <cstdint>
#include <cstddef>

#define DD 128
#define VMAX 100000
#define EMAX 524288

// ---------------------------------------------------------------------------
// Global scratch (no allocs allowed)
// ---------------------------------------------------------------------------
__device__ float g_Y[2u * VMAX * DD];             // Y_in | Y_out, fp32
__device__ float g_stats[2 * DD];                 // BN sum / sumsq
__device__ __align__(16) unsigned char g_Bh[6 * 16384];  // W fp16 image
__device__ int g_deg[2 * VMAX];                   // per (dir,node) degree
__device__ int g_off[2 * VMAX + 1];               // CSR offsets
__device__ int g_cur[2 * VMAX];                   // fill cursors
__device__ int g_eid[EMAX];                       // dst-sorted edge ids

// ---------------------------------------------------------------------------
// PTX helpers (generic-target safe: ldmatrix + mma.sync + cp.async)
// ---------------------------------------------------------------------------
__device__ __forceinline__ uint32_t smem_u32(const void* p) {
    uint32_t a;
    asm("{ .reg .u64 t; cvta.to.shared.u64 t, %1; cvt.u32.u64 %0, t; }" : "=r"(a) : "l"(p));
    return a;
}

#define LDSM4(r, addr)                                                          \
    asm volatile("ldmatrix.sync.aligned.m8n8.x4.shared.b16 {%0,%1,%2,%3}, [%4];" \
        : "=r"((r)[0]), "=r"((r)[1]), "=r"((r)[2]), "=r"((r)[3]) : "r"(addr))

#define MMA16816F16(d, a, b0, b1)                                               \
    asm volatile("mma.sync.aligned.m16n8k16.row.col.f32.f16.f16.f32 "           \
        "{%0,%1,%2,%3}, {%4,%5,%6,%7}, {%8,%9}, {%0,%1,%2,%3};"                 \
        : "+f"((d)[0]), "+f"((d)[1]), "+f"((d)[2]), "+f"((d)[3])                \
        : "r"((a)[0]), "r"((a)[1]), "r"((a)[2]), "r"((a)[3]), "r"(b0), "r"(b1))

#define CP_ASYNC16(saddr, gptr)                                                 \
    asm volatile("cp.async.cg.shared.global [%0], [%1], 16;"                    \
        :: "r"(saddr), "l"(gptr) : "memory")
#define CP_COMMIT()  asm volatile("cp.async.commit_group;" ::: "memory")
#define CP_WAIT0()   asm volatile("cp.async.wait_group 0;" ::: "memory")

// fp16 split: hi = rn(z), lo = rn(z - hi).
__device__ __forceinline__ void split4h(const float4 z, uint2& hi, uint2& lo) {
    __half2 h01 = __floats2half2_rn(z.x, z.y);
    __half2 h23 = __floats2half2_rn(z.z, z.w);
    float2 f01 = __half22float2(h01);
    float2 f23 = __half22float2(h23);
    __half2 l01 = __floats2half2_rn(z.x - f01.x, z.y - f01.y);
    __half2 l23 = __floats2half2_rn(z.z - f23.x, z.w - f23.y);
    hi.x = *reinterpret_cast<uint32_t*>(&h01);
    hi.y = *reinterpret_cast<uint32_t*>(&h23);
    lo.x = *reinterpret_cast<uint32_t*>(&l01);
    lo.y = *reinterpret_cast<uint32_t*>(&l23);
}

// ---------------------------------------------------------------------------
// Kernel 0: W image, fp16, 6 chunks of [128 n][64 k]. loop_rel folded in.
// ---------------------------------------------------------------------------
__global__ void prep_w(const float* __restrict__ in_w, const float* __restrict__ out_w,
                       const float* __restrict__ loop_w,
                       const float* __restrict__ loop_rel) {
    int c = blockIdx.x;
    const float* W = (c < 2) ? in_w : (c < 4 ? out_w : loop_w);
    int k0 = (c & 1) * 64;
    __half* bh = reinterpret_cast<__half*>(g_Bh + c * 16384);
    for (int i = threadIdx.x; i < 8192; i += blockDim.x) {
        int n = i >> 6, k = i & 63;
        float v = W[(size_t)(k0 + k) * DD + n];
        if (c >= 4) v *= loop_rel[k0 + k];
        bh[n * 64 + k] = __float2half_rn(v);
    }
}

// ---------------------------------------------------------------------------
// CSR build: histogram -> single-kernel scan -> fill
// ---------------------------------------------------------------------------
__global__ void hist_kernel(const int* __restrict__ dst, int E, int half, int V) {
    int e = blockIdx.x * blockDim.x + threadIdx.x;
    if (e >= E) return;
    int node = (e < half ? 0 : V) + __ldg(&dst[e]);
    atomicAdd(&g_deg[node], 1);
}

// One block, 1024 threads: chunked exclusive scan of g_deg into g_off/g_cur.
__global__ void scan_kernel(int N) {
    __shared__ int sh[1024];
    int t = threadIdx.x;
    int chunk = (N + 1023) >> 10;
    int beg = t * chunk;
    int end = min(beg + chunk, N);
    if (beg > N) { beg = N; end = N; }
    int s = 0;
    for (int i = beg; i < end; i++) s += g_deg[i];
    sh[t] = s;
    __syncthreads();
    for (int off = 1; off < 1024; off <<= 1) {
        int v = (t >= off) ? sh[t - off] : 0;
        __syncthreads();
        sh[t] += v;
        __syncthreads();
    }
    int run = sh[t] - s;   // exclusive prefix of this thread's chunk
    for (int i = beg; i < end; i++) {
        int d = g_deg[i];
        g_off[i] = run;
        g_cur[i] = run;
        run += d;
    }
    if (t == 1023) g_off[N] = sh[1023];
}

__global__ void fill_kernel(const int* __restrict__ dst, int E, int half, int V) {
    int e = blockIdx.x * blockDim.x + threadIdx.x;
    if (e >= E) return;
    int node = (e < half ? 0 : V) + __ldg(&dst[e]);
    int pos = atomicAdd(&g_cur[node], 1);
    g_eid[pos] = e;
}

// ---------------------------------------------------------------------------
// Gather v2: warp = 4 edge-groups x 8 lanes. lane = g*8 + l.
// Group g processes edge (base+g); lane covers channels [l*16, l*16+16).
// 4 edges in flight -> MLP ~8 per lane; predicated loads (no waste);
// one cross-group shfl reduction per ROW; row written exactly once.
// ---------------------------------------------------------------------------
__global__ void gather_kernel(const float* __restrict__ x,
                              const float* __restrict__ rel,
                              const float* __restrict__ enorm,
                              const int* __restrict__ src,
                              const int* __restrict__ et,
                              int N) {
    int gw = (blockIdx.x * blockDim.x + threadIdx.x) >> 5;
    if (gw >= N) return;
    int lane = threadIdx.x & 31;
    int g = lane >> 3;       // edge slot 0..3
    int l = lane & 7;        // channel slice (16 floats)

    int start = __ldg(&g_off[gw]);
    int end   = __ldg(&g_off[gw + 1]);

    float4 a0 = make_float4(0.f, 0.f, 0.f, 0.f);
    float4 a1 = a0, a2 = a0, a3 = a0;

    for (int base = start; base < end; base += 4) {
        int j = base + g;
        if (j < end) {
            int e = __ldg(&g_eid[j]);
            int   ss = __ldg(&src[e]);
            int   tt = __ldg(&et[e]);
            float nn = __ldg(&enorm[e]);
            const float4* xp = reinterpret_cast<const float4*>(x)   + (size_t)ss * 32 + l * 4;
            const float4* rp = reinterpret_cast<const float4*>(rel) + (size_t)tt * 32 + l * 4;
            float4 x0 = __ldg(xp + 0), x1 = __ldg(xp + 1);
            float4 x2 = __ldg(xp + 2), x3 = __ldg(xp + 3);
            float4 r0 = __ldg(rp + 0), r1 = __ldg(rp + 1);
            float4 r2 = __ldg(rp + 2), r3 = __ldg(rp + 3);
            a0.x += nn * x0.x * r0.x; a0.y += nn * x0.y * r0.y;
            a0.z += nn * x0.z * r0.z; a0.w += nn * x0.w * r0.w;
            a1.x += nn * x1.x * r1.x; a1.y += nn * x1.y * r1.y;
            a1.z += nn * x1.z * r1.z; a1.w += nn * x1.w * r1.w;
            a2.x += nn * x2.x * r2.x; a2.y += nn * x2.y * r2.y;
            a2.z += nn * x2.z * r2.z; a2.w += nn * x2.w * r2.w;
            a3.x += nn * x3.x * r3.x; a3.y += nn * x3.y * r3.y;
            a3.z += nn * x3.z * r3.z; a3.w += nn * x3.w * r3.w;
        }
    }

    // reduce across the 4 groups (lane bits 3 and 4)
#pragma unroll
    for (int off = 8; off <= 16; off <<= 1) {
        a0.x += __shfl_xor_sync(0xFFFFFFFFu, a0.x, off);
        a0.y += __shfl_xor_sync(0xFFFFFFFFu, a0.y, off);
        a0.z += __shfl_xor_sync(0xFFFFFFFFu, a0.z, off);
        a0.w += __shfl_xor_sync(0xFFFFFFFFu, a0.w, off);
        a1.x += __shfl_xor_sync(0xFFFFFFFFu, a1.x, off);
        a1.y += __shfl_xor_sync(0xFFFFFFFFu, a1.y, off);
        a1.z += __shfl_xor_sync(0xFFFFFFFFu, a1.z, off);
        a1.w += __shfl_xor_sync(0xFFFFFFFFu, a1.w, off);
        a2.x += __shfl_xor_sync(0xFFFFFFFFu, a2.x, off);
        a2.y += __shfl_xor_sync(0xFFFFFFFFu, a2.y, off);
        a2.z += __shfl_xor_sync(0xFFFFFFFFu, a2.z, off);
        a2.w += __shfl_xor_sync(0xFFFFFFFFu, a2.w, off);
        a3.x += __shfl_xor_sync(0xFFFFFFFFu, a3.x, off);
        a3.y += __shfl_xor_sync(0xFFFFFFFFu, a3.y, off);
        a3.z += __shfl_xor_sync(0xFFFFFFFFu, a3.z, off);
        a3.w += __shfl_xor_sync(0xFFFFFFFFu, a3.w, off);
    }
    if (g == 0) {
        float4* yp = reinterpret_cast<float4*>(g_Y + (size_t)gw * DD + l * 16);
        yp[0] = a0; yp[1] = a1; yp[2] = a2; yp[3] = a3;
    }
}

// ---------------------------------------------------------------------------
// GEMM: mma.sync fp16 hi/lo, 2 passes, K-chunks of 64 (6 iterations).
// ---------------------------------------------------------------------------
#define ROWB 144
#define OAH 0
#define OAL 18432
#define OBH 36864
#define SMEM_GEMM 55296

__global__ void __launch_bounds__(256, 2) gemm_mma(
    const float* __restrict__ x,
    const float* __restrict__ bias,
    float* __restrict__ hout,
    int V) {

    extern __shared__ __align__(16) unsigned char sm[];
    const uint32_t sb = smem_u32(sm);
    const uint32_t uAh = sb + OAH;
    const uint32_t uAl = sb + OAL;
    const uint32_t uBh = sb + OBH;

    const int tid  = threadIdx.x;
    const int wid  = tid >> 5;
    const int lane = tid & 31;
    const int wm   = wid & 3;
    const int wn   = wid >> 2;
    const int m0   = blockIdx.x * 128;

    float acc[2][8][4];
#pragma unroll
    for (int i = 0; i < 2; i++)
#pragma unroll
        for (int j = 0; j < 8; j++)
#pragma unroll
            for (int k = 0; k < 4; k++) acc[i][j][k] = 0.f;

    for (int c = 0; c < 6; c++) {
        __syncthreads();
        {
            const unsigned char* gh = g_Bh + c * 16384;
#pragma unroll
            for (int j = 0; j < 4; j++) {
                int i = tid + j * 256;
                int r = i >> 3, g = i & 7;
                CP_ASYNC16(uBh + r * ROWB + g * 16, gh + r * 128 + g * 16);
            }
            CP_COMMIT();
        }
        {
            const int k0 = (c & 1) * 64;
            const float* Ab = (c < 2) ? g_Y : (c < 4 ? g_Y + (size_t)V * DD : x);
#pragma unroll
            for (int j = 0; j < 8; j++) {
                int i = tid + j * 256;
                int r = i >> 4, g = i & 15;
                int v = m0 + r;
                float4 z = make_float4(0.f, 0.f, 0.f, 0.f);
                if (v < V)
                    z = *reinterpret_cast<const float4*>(Ab + (size_t)v * DD + k0 + g * 4);
                uint2 hi, lo;
                split4h(z, hi, lo);
                *reinterpret_cast<uint2*>(sm + OAH + r * ROWB + g * 8) = hi;
                *reinterpret_cast<uint2*>(sm + OAL + r * ROWB + g * 8) = lo;
            }
        }
        CP_WAIT0();
        __syncthreads();

#pragma unroll
        for (int k16 = 0; k16 < 4; k16++) {
            const uint32_t kb = k16 * 32 + ((lane >> 4) << 4);
            const uint32_t arow = (uint32_t)(wm * 32 + (lane & 15)) * ROWB + kb;
            const uint32_t brow = (uint32_t)(wn * 64 + (lane & 15)) * ROWB + kb;

            uint32_t ah[2][4], al[2][4], bb[4][4];
#pragma unroll
            for (int mt = 0; mt < 2; mt++) LDSM4(ah[mt], uAh + arow + mt * 16 * ROWB);
#pragma unroll
            for (int nb = 0; nb < 4; nb++) LDSM4(bb[nb], uBh + brow + nb * 16 * ROWB);
#pragma unroll
            for (int mt = 0; mt < 2; mt++)
#pragma unroll
                for (int nb = 0; nb < 4; nb++) {
                    MMA16816F16(acc[mt][nb * 2 + 0], ah[mt], bb[nb][0], bb[nb][2]);
                    MMA16816F16(acc[mt][nb * 2 + 1], ah[mt], bb[nb][1], bb[nb][3]);
                }
#pragma unroll
            for (int mt = 0; mt < 2; mt++) LDSM4(al[mt], uAl + arow + mt * 16 * ROWB);
#pragma unroll
            for (int mt = 0; mt < 2; mt++)
#pragma unroll
                for (int nb = 0; nb < 4; nb++) {
                    MMA16816F16(acc[mt][nb * 2 + 0], al[mt], bb[nb][0], bb[nb][2]);
                    MMA16816F16(acc[mt][nb * 2 + 1], al[mt], bb[nb][1], bb[nb][3]);
                }
        }
    }

    // ---- epilogue: /3 + bias, store h, accumulate BN stats ----
    const float third = 1.f / 3.f;
    float ssum[16], ssq[16];
#pragma unroll
    for (int i = 0; i < 16; i++) { ssum[i] = 0.f; ssq[i] = 0.f; }

#pragma unroll
    for (int mt = 0; mt < 2; mt++) {
        int rowa = m0 + wm * 32 + mt * 16 + (lane >> 2);
        int rowb = rowa + 8;
#pragma unroll
        for (int nt = 0; nt < 8; nt++) {
            int col = wn * 64 + nt * 8 + (lane & 3) * 2;
            float2 bv = *reinterpret_cast<const float2*>(bias + col);
            float h0 = acc[mt][nt][0] * third + bv.x;
            float h1 = acc[mt][nt][1] * third + bv.y;
            float h2 = acc[mt][nt][2] * third + bv.x;
            float h3 = acc[mt][nt][3] * third + bv.y;
            if (rowa < V) {
                *reinterpret_cast<float2*>(hout + (size_t)rowa * DD + col) =
                    make_float2(h0, h1);
                ssum[nt * 2 + 0] += h0; ssq[nt * 2 + 0] += h0 * h0;
                ssum[nt * 2 + 1] += h1; ssq[nt * 2 + 1] += h1 * h1;
            }
            if (rowb < V) {
                *reinterpret_cast<float2*>(hout + (size_t)rowb * DD + col) =
                    make_float2(h2, h3);
                ssum[nt * 2 + 0] += h2; ssq[nt * 2 + 0] += h2 * h2;
                ssum[nt * 2 + 1] += h3; ssq[nt * 2 + 1] += h3 * h3;
            }
        }
    }
#pragma unroll
    for (int i = 0; i < 16; i++) {
#pragma unroll
        for (int off = 4; off <= 16; off <<= 1) {
            ssum[i] += __shfl_xor_sync(0xFFFFFFFFu, ssum[i], off);
            ssq[i]  += __shfl_xor_sync(0xFFFFFFFFu, ssq[i],  off);
        }
    }
    __syncthreads();
    float* Ssum = reinterpret_cast<float*>(sm);
    float* Ssq  = reinterpret_cast<float*>(sm + 4096);
#pragma unroll
    for (int j = 0; j < 4; j++) { Ssum[tid + j * 256] = 0.f; Ssq[tid + j * 256] = 0.f; }
    __syncthreads();
    if (lane < 4) {
#pragma unroll
        for (int nt = 0; nt < 8; nt++) {
            int col = wn * 64 + nt * 8 + lane * 2;
            Ssum[wid * 128 + col]     = ssum[nt * 2 + 0];
            Ssum[wid * 128 + col + 1] = ssum[nt * 2 + 1];
            Ssq [wid * 128 + col]     = ssq[nt * 2 + 0];
            Ssq [wid * 128 + col + 1] = ssq[nt * 2 + 1];
        }
    }
    __syncthreads();
    if (tid < 128) {
        float a = 0.f, b = 0.f;
#pragma unroll
        for (int w = 0; w < 8; w++) { a += Ssum[w * 128 + tid]; b += Ssq[w * 128 + tid]; }
        atomicAdd(&g_stats[tid],       a);
        atomicAdd(&g_stats[128 + tid], b);
    }
}

// ---------------------------------------------------------------------------
// BatchNorm + ReLU, in place on h
// ---------------------------------------------------------------------------
__global__ void bn_kernel(float* __restrict__ h, int V) {
    __shared__ float ms[128];
    __shared__ float rs[128];
    if (threadIdx.x < 128) {
        float invn = 1.f / (float)V;
        float s  = g_stats[threadIdx.x];
        float sq = g_stats[128 + threadIdx.x];
        float m  = s * invn;
        float var = sq * invn - m * m;
        ms[threadIdx.x] = m;
        rs[threadIdx.x] = rsqrtf(var + 1e-5f);
    }
    __syncthreads();
    size_t total = (size_t)V * 32;
    float4* h4 = reinterpret_cast<float4*>(h);
    for (size_t i = (size_t)blockIdx.x * blockDim.x + threadIdx.x; i < total;
         i += (size_t)gridDim.x * blockDim.x) {
        int c4 = (int)(i & 31) * 4;
        float4 hv = h4[i];
        hv.x = fmaxf((hv.x - ms[c4 + 0]) * rs[c4 + 0], 0.f);
        hv.y = fmaxf((hv.y - ms[c4 + 1]) * rs[c4 + 1], 0.f);
        hv.z = fmaxf((hv.z - ms[c4 + 2]) * rs[c4 + 2], 0.f);
        hv.w = fmaxf((hv.w - ms[c4 + 3]) * rs[c4 + 3], 0.f);
        h4[i] = hv;
    }
}

// ---------------------------------------------------------------------------
// rel_repr @ w_rel, 4 rel rows per block
// ---------------------------------------------------------------------------
__global__ void relw_kernel(const float* __restrict__ rel,
                            const float* __restrict__ w_rel,
                            float* __restrict__ out, int R) {
    __shared__ float rr[4][128];
    int r0 = blockIdx.x * 4;
    int c = threadIdx.x;
#pragma unroll
    for (int j = 0; j < 4; j++)
        rr[j][c] = (r0 + j < R) ? rel[(size_t)(r0 + j) * DD + c] : 0.f;
    __syncthreads();
    float a0 = 0.f, a1 = 0.f, a2 = 0.f, a3 = 0.f;
#pragma unroll 4
    for (int k = 0; k < 128; k++) {
        float w = __ldg(&w_rel[(size_t)k * DD + c]);
        a0 += rr[0][k] * w;
        a1 += rr[1][k] * w;
        a2 += rr[2][k] * w;
        a3 += rr[3][k] * w;
    }
    if (r0 + 0 < R) out[(size_t)(r0 + 0) * DD + c] = a0;
    if (r0 + 1 < R) out[(size_t)(r0 + 1) * DD + c] = a1;
    if (r0 + 2 < R) out[(size_t)(r0 + 2) * DD + c] = a2;
    if (r0 + 3 < R) out[(size_t)(r0 + 3) * DD + c] = a3;
}

// ---------------------------------------------------------------------------
extern "C" void kernel_launch(void* const* d_in, const int* in_sizes, int n_in,
                              void* d_out, int out_size) {
    const float* x        = (const float*)d_in[0];
    const float* rel      = (const float*)d_in[1];
    const float* enorm    = (const float*)d_in[2];
    const float* in_w     = (const float*)d_in[3];
    const float* out_w    = (const float*)d_in[4];
    const float* loop_w   = (const float*)d_in[5];
    const float* w_rel    = (const float*)d_in[6];
    const float* loop_rel = (const float*)d_in[7];
    const float* bias     = (const float*)d_in[8];
    const int*   src      = (const int*)d_in[9];
    const int*   dst      = (const int*)d_in[10];
    const int*   et       = (const int*)d_in[11];

    int V = in_sizes[0] / DD;
    int R = in_sizes[1] / DD;
    int E = in_sizes[2];
    int half = E / 2;
    int N = 2 * V;

    float* h    = (float*)d_out;
    float* out2 = h + (size_t)V * DD;

    void* dptr = nullptr; void* sptr = nullptr;
    cudaGetSymbolAddress(&dptr, g_deg);
    cudaGetSymbolAddress(&sptr, g_stats);
    cudaMemsetAsync(dptr, 0, (size_t)N * sizeof(int), 0);
    cudaMemsetAsync(sptr, 0, 2 * DD * sizeof(float), 0);

    cudaFuncSetAttribute(gemm_mma, cudaFuncAttributeMaxDynamicSharedMemorySize,
                         SMEM_GEMM);

    prep_w<<<6, 256>>>(in_w, out_w, loop_w, loop_rel);
    hist_kernel<<<(E + 255) / 256, 256>>>(dst, E, half, V);
    scan_kernel<<<1, 1024>>>(N);
    fill_kernel<<<(E + 255) / 256, 256>>>(dst, E, half, V);
    gather_kernel<<<(N + 7) / 8, 256>>>(x, rel, enorm, src, et, N);
    gemm_mma<<<(V + 127) / 128, 256, SMEM_GEMM>>>(x, bias, h, V);
    bn_kernel<<<1024, 256>>>(h, V);
    relw_kernel<<<(R + 3) / 4, 128>>>(rel, w_rel, out2, R);
}

// round 15
// speedup vs baseline: 2.1926x; 2.1926x over previous
#include <cuda_runtime.h>
#include <cuda_fp16.h>
#include <cstdint>
#include <cstddef>

#define DD 128
#define VMAX 100000
#define EMAX 524288

// ---------------------------------------------------------------------------
// Global scratch (no allocs allowed)
// ---------------------------------------------------------------------------
__device__ float g_Y[2u * VMAX * DD];             // Y_in | Y_out, fp32
__device__ float g_stats[2 * DD];                 // BN sum / sumsq
__device__ __align__(16) unsigned char g_Bh[6 * 16384];  // W fp16 image
__device__ int g_deg[2 * VMAX];                   // per (dir,node) degree
__device__ int g_off[2 * VMAX + 1];               // CSR offsets
__device__ int g_cur[2 * VMAX];                   // fill cursors
__device__ int g_eid[EMAX];                       // dst-sorted edge ids
__device__ int g_bsum[256];                       // scan block sums

// ---------------------------------------------------------------------------
// PTX helpers (generic-target safe: ldmatrix + mma.sync + cp.async)
// ---------------------------------------------------------------------------
__device__ __forceinline__ uint32_t smem_u32(const void* p) {
    uint32_t a;
    asm("{ .reg .u64 t; cvta.to.shared.u64 t, %1; cvt.u32.u64 %0, t; }" : "=r"(a) : "l"(p));
    return a;
}

#define LDSM4(r, addr)                                                          \
    asm volatile("ldmatrix.sync.aligned.m8n8.x4.shared.b16 {%0,%1,%2,%3}, [%4];" \
        : "=r"((r)[0]), "=r"((r)[1]), "=r"((r)[2]), "=r"((r)[3]) : "r"(addr))

#define MMA16816F16(d, a, b0, b1)                                               \
    asm volatile("mma.sync.aligned.m16n8k16.row.col.f32.f16.f16.f32 "           \
        "{%0,%1,%2,%3}, {%4,%5,%6,%7}, {%8,%9}, {%0,%1,%2,%3};"                 \
        : "+f"((d)[0]), "+f"((d)[1]), "+f"((d)[2]), "+f"((d)[3])                \
        : "r"((a)[0]), "r"((a)[1]), "r"((a)[2]), "r"((a)[3]), "r"(b0), "r"(b1))

#define CP_ASYNC16(saddr, gptr)                                                 \
    asm volatile("cp.async.cg.shared.global [%0], [%1], 16;"                    \
        :: "r"(saddr), "l"(gptr) : "memory")
#define CP_COMMIT()  asm volatile("cp.async.commit_group;" ::: "memory")
#define CP_WAIT0()   asm volatile("cp.async.wait_group 0;" ::: "memory")

// fp16 split: hi = rn(z), lo = rn(z - hi).
__device__ __forceinline__ void split4h(const float4 z, uint2& hi, uint2& lo) {
    __half2 h01 = __floats2half2_rn(z.x, z.y);
    __half2 h23 = __floats2half2_rn(z.z, z.w);
    float2 f01 = __half22float2(h01);
    float2 f23 = __half22float2(h23);
    __half2 l01 = __floats2half2_rn(z.x - f01.x, z.y - f01.y);
    __half2 l23 = __floats2half2_rn(z.z - f23.x, z.w - f23.y);
    hi.x = *reinterpret_cast<uint32_t*>(&h01);
    hi.y = *reinterpret_cast<uint32_t*>(&h23);
    lo.x = *reinterpret_cast<uint32_t*>(&l01);
    lo.y = *reinterpret_cast<uint32_t*>(&l23);
}

// ---------------------------------------------------------------------------
// Kernel 0: W image, fp16, 6 chunks of [128 n][64 k]. loop_rel folded in.
// ---------------------------------------------------------------------------
__global__ void prep_w(const float* __restrict__ in_w, const float* __restrict__ out_w,
                       const float* __restrict__ loop_w,
                       const float* __restrict__ loop_rel) {
    int c = blockIdx.x;
    const float* W = (c < 2) ? in_w : (c < 4 ? out_w : loop_w);
    int k0 = (c & 1) * 64;
    __half* bh = reinterpret_cast<__half*>(g_Bh + c * 16384);
    for (int i = threadIdx.x; i < 8192; i += blockDim.x) {
        int n = i >> 6, k = i & 63;
        float v = W[(size_t)(k0 + k) * DD + n];
        if (c >= 4) v *= loop_rel[k0 + k];
        bh[n * 64 + k] = __float2half_rn(v);
    }
}

// ---------------------------------------------------------------------------
// CSR build: histogram -> 3-kernel scan (parallel scan2) -> fill
// ---------------------------------------------------------------------------
__global__ void hist_kernel(const int* __restrict__ dst, int E, int half, int V) {
    int e = blockIdx.x * blockDim.x + threadIdx.x;
    if (e >= E) return;
    int node = (e < half ? 0 : V) + __ldg(&dst[e]);
    atomicAdd(&g_deg[node], 1);
}

// scan1: per-1024-block sums of g_deg
__global__ void scan1_kernel(int N) {
    __shared__ int sh[256];
    int b = blockIdx.x, t = threadIdx.x;
    int base = b * 1024 + t * 4;
    int s = 0;
#pragma unroll
    for (int j = 0; j < 4; j++) {
        int idx = base + j;
        if (idx < N) s += g_deg[idx];
    }
    sh[t] = s;
    __syncthreads();
    for (int off = 128; off > 0; off >>= 1) {
        if (t < off) sh[t] += sh[t + off];
        __syncthreads();
    }
    if (t == 0) g_bsum[b] = sh[0];
}

// scan2: PARALLEL exclusive scan of <=256 block sums (one block, 256 threads)
__global__ void scan2_kernel(int NB, int N) {
    __shared__ int sh[256];
    int t = threadIdx.x;
    int v = (t < NB) ? g_bsum[t] : 0;
    sh[t] = v;
    __syncthreads();
    for (int off = 1; off < 256; off <<= 1) {
        int u = (t >= off) ? sh[t - off] : 0;
        __syncthreads();
        sh[t] += u;
        __syncthreads();
    }
    if (t < NB) g_bsum[t] = sh[t] - v;    // exclusive
    if (t == 255) g_off[N] = sh[255];     // grand total
}

// scan3: per-block exclusive scan + block offset; writes g_off and g_cur
__global__ void scan3_kernel(int N) {
    __shared__ int sh[256];
    int b = blockIdx.x, t = threadIdx.x;
    int base = b * 1024 + t * 4;
    int v[4];
    int s = 0;
#pragma unroll
    for (int j = 0; j < 4; j++) {
        int idx = base + j;
        v[j] = (idx < N) ? g_deg[idx] : 0;
        s += v[j];
    }
    sh[t] = s;
    __syncthreads();
    for (int off = 1; off < 256; off <<= 1) {
        int tmp = (t >= off) ? sh[t - off] : 0;
        __syncthreads();
        sh[t] += tmp;
        __syncthreads();
    }
    int excl = g_bsum[b] + sh[t] - s;
#pragma unroll
    for (int j = 0; j < 4; j++) {
        int idx = base + j;
        if (idx < N) {
            g_off[idx] = excl;
            g_cur[idx] = excl;
        }
        excl += v[j];
    }
}

__global__ void fill_kernel(const int* __restrict__ dst, int E, int half, int V) {
    int e = blockIdx.x * blockDim.x + threadIdx.x;
    if (e >= E) return;
    int node = (e < half ? 0 : V) + __ldg(&dst[e]);
    int pos = atomicAdd(&g_cur[node], 1);
    g_eid[pos] = e;
}

// ---------------------------------------------------------------------------
// Gather v2: warp = 4 edge-groups x 8 lanes. lane = g*8 + l.
// Group g processes edge (base+g); lane covers channels [l*16, l*16+16).
// 4 edges in flight -> MLP ~8 per lane; predicated loads (no waste);
// cross-group shfl reduction once per row; row written exactly once.
// ---------------------------------------------------------------------------
__global__ void gather_kernel(const float* __restrict__ x,
                              const float* __restrict__ rel,
                              const float* __restrict__ enorm,
                              const int* __restrict__ src,
                              const int* __restrict__ et,
                              int N) {
    int gw = (blockIdx.x * blockDim.x + threadIdx.x) >> 5;
    if (gw >= N) return;
    int lane = threadIdx.x & 31;
    int g = lane >> 3;       // edge slot 0..3
    int l = lane & 7;        // channel slice (16 floats)

    int start = __ldg(&g_off[gw]);
    int end   = __ldg(&g_off[gw + 1]);

    float4 a0 = make_float4(0.f, 0.f, 0.f, 0.f);
    float4 a1 = a0, a2 = a0, a3 = a0;

    for (int base = start; base < end; base += 4) {
        int j = base + g;
        if (j < end) {
            int e = __ldg(&g_eid[j]);
            int   ss = __ldg(&src[e]);
            int   tt = __ldg(&et[e]);
            float nn = __ldg(&enorm[e]);
            const float4* xp = reinterpret_cast<const float4*>(x)   + (size_t)ss * 32 + l * 4;
            const float4* rp = reinterpret_cast<const float4*>(rel) + (size_t)tt * 32 + l * 4;
            float4 x0 = __ldg(xp + 0), x1 = __ldg(xp + 1);
            float4 x2 = __ldg(xp + 2), x3 = __ldg(xp + 3);
            float4 r0 = __ldg(rp + 0), r1 = __ldg(rp + 1);
            float4 r2 = __ldg(rp + 2), r3 = __ldg(rp + 3);
            a0.x += nn * x0.x * r0.x; a0.y += nn * x0.y * r0.y;
            a0.z += nn * x0.z * r0.z; a0.w += nn * x0.w * r0.w;
            a1.x += nn * x1.x * r1.x; a1.y += nn * x1.y * r1.y;
            a1.z += nn * x1.z * r1.z; a1.w += nn * x1.w * r1.w;
            a2.x += nn * x2.x * r2.x; a2.y += nn * x2.y * r2.y;
            a2.z += nn * x2.z * r2.z; a2.w += nn * x2.w * r2.w;
            a3.x += nn * x3.x * r3.x; a3.y += nn * x3.y * r3.y;
            a3.z += nn * x3.z * r3.z; a3.w += nn * x3.w * r3.w;
        }
    }

#pragma unroll
    for (int off = 8; off <= 16; off <<= 1) {
        a0.x += __shfl_xor_sync(0xFFFFFFFFu, a0.x, off);
        a0.y += __shfl_xor_sync(0xFFFFFFFFu, a0.y, off);
        a0.z += __shfl_xor_sync(0xFFFFFFFFu, a0.z, off);
        a0.w += __shfl_xor_sync(0xFFFFFFFFu, a0.w, off);
        a1.x += __shfl_xor_sync(0xFFFFFFFFu, a1.x, off);
        a1.y += __shfl_xor_sync(0xFFFFFFFFu, a1.y, off);
        a1.z += __shfl_xor_sync(0xFFFFFFFFu, a1.z, off);
        a1.w += __shfl_xor_sync(0xFFFFFFFFu, a1.w, off);
        a2.x += __shfl_xor_sync(0xFFFFFFFFu, a2.x, off);
        a2.y += __shfl_xor_sync(0xFFFFFFFFu, a2.y, off);
        a2.z += __shfl_xor_sync(0xFFFFFFFFu, a2.z, off);
        a2.w += __shfl_xor_sync(0xFFFFFFFFu, a2.w, off);
        a3.x += __shfl_xor_sync(0xFFFFFFFFu, a3.x, off);
        a3.y += __shfl_xor_sync(0xFFFFFFFFu, a3.y, off);
        a3.z += __shfl_xor_sync(0xFFFFFFFFu, a3.z, off);
        a3.w += __shfl_xor_sync(0xFFFFFFFFu, a3.w, off);
    }
    if (g == 0) {
        float4* yp = reinterpret_cast<float4*>(g_Y + (size_t)gw * DD + l * 16);
        yp[0] = a0; yp[1] = a1; yp[2] = a2; yp[3] = a3;
    }
}

// ---------------------------------------------------------------------------
// GEMM: mma.sync fp16 hi/lo, 2 passes, K-chunks of 64 (6 iterations).
// ---------------------------------------------------------------------------
#define ROWB 144
#define OAH 0
#define OAL 18432
#define OBH 36864
#define SMEM_GEMM 55296

__global__ void __launch_bounds__(256, 2) gemm_mma(
    const float* __restrict__ x,
    const float* __restrict__ bias,
    float* __restrict__ hout,
    int V) {

    extern __shared__ __align__(16) unsigned char sm[];
    const uint32_t sb = smem_u32(sm);
    const uint32_t uAh = sb + OAH;
    const uint32_t uAl = sb + OAL;
    const uint32_t uBh = sb + OBH;

    const int tid  = threadIdx.x;
    const int wid  = tid >> 5;
    const int lane = tid & 31;
    const int wm   = wid & 3;
    const int wn   = wid >> 2;
    const int m0   = blockIdx.x * 128;

    float acc[2][8][4];
#pragma unroll
    for (int i = 0; i < 2; i++)
#pragma unroll
        for (int j = 0; j < 8; j++)
#pragma unroll
            for (int k = 0; k < 4; k++) acc[i][j][k] = 0.f;

    for (int c = 0; c < 6; c++) {
        __syncthreads();
        {
            const unsigned char* gh = g_Bh + c * 16384;
#pragma unroll
            for (int j = 0; j < 4; j++) {
                int i = tid + j * 256;
                int r = i >> 3, g = i & 7;
                CP_ASYNC16(uBh + r * ROWB + g * 16, gh + r * 128 + g * 16);
            }
            CP_COMMIT();
        }
        {
            const int k0 = (c & 1) * 64;
            const float* Ab = (c < 2) ? g_Y : (c < 4 ? g_Y + (size_t)V * DD : x);
#pragma unroll
            for (int j = 0; j < 8; j++) {
                int i = tid + j * 256;
                int r = i >> 4, g = i & 15;
                int v = m0 + r;
                float4 z = make_float4(0.f, 0.f, 0.f, 0.f);
                if (v < V)
                    z = *reinterpret_cast<const float4*>(Ab + (size_t)v * DD + k0 + g * 4);
                uint2 hi, lo;
                split4h(z, hi, lo);
                *reinterpret_cast<uint2*>(sm + OAH + r * ROWB + g * 8) = hi;
                *reinterpret_cast<uint2*>(sm + OAL + r * ROWB + g * 8) = lo;
            }
        }
        CP_WAIT0();
        __syncthreads();

#pragma unroll
        for (int k16 = 0; k16 < 4; k16++) {
            const uint32_t kb = k16 * 32 + ((lane >> 4) << 4);
            const uint32_t arow = (uint32_t)(wm * 32 + (lane & 15)) * ROWB + kb;
            const uint32_t brow = (uint32_t)(wn * 64 + (lane & 15)) * ROWB + kb;

            uint32_t ah[2][4], al[2][4], bb[4][4];
#pragma unroll
            for (int mt = 0; mt < 2; mt++) LDSM4(ah[mt], uAh + arow + mt * 16 * ROWB);
#pragma unroll
            for (int nb = 0; nb < 4; nb++) LDSM4(bb[nb], uBh + brow + nb * 16 * ROWB);
#pragma unroll
            for (int mt = 0; mt < 2; mt++)
#pragma unroll
                for (int nb = 0; nb < 4; nb++) {
                    MMA16816F16(acc[mt][nb * 2 + 0], ah[mt], bb[nb][0], bb[nb][2]);
                    MMA16816F16(acc[mt][nb * 2 + 1], ah[mt], bb[nb][1], bb[nb][3]);
                }
#pragma unroll
            for (int mt = 0; mt < 2; mt++) LDSM4(al[mt], uAl + arow + mt * 16 * ROWB);
#pragma unroll
            for (int mt = 0; mt < 2; mt++)
#pragma unroll
                for (int nb = 0; nb < 4; nb++) {
                    MMA16816F16(acc[mt][nb * 2 + 0], al[mt], bb[nb][0], bb[nb][2]);
                    MMA16816F16(acc[mt][nb * 2 + 1], al[mt], bb[nb][1], bb[nb][3]);
                }
        }
    }

    // ---- epilogue: /3 + bias, store h, accumulate BN stats ----
    const float third = 1.f / 3.f;
    float ssum[16], ssq[16];
#pragma unroll
    for (int i = 0; i < 16; i++) { ssum[i] = 0.f; ssq[i] = 0.f; }

#pragma unroll
    for (int mt = 0; mt < 2; mt++) {
        int rowa = m0 + wm * 32 + mt * 16 + (lane >> 2);
        int rowb = rowa + 8;
#pragma unroll
        for (int nt = 0; nt < 8; nt++) {
            int col = wn * 64 + nt * 8 + (lane & 3) * 2;
            float2 bv = *reinterpret_cast<const float2*>(bias + col);
            float h0 = acc[mt][nt][0] * third + bv.x;
            float h1 = acc[mt][nt][1] * third + bv.y;
            float h2 = acc[mt][nt][2] * third + bv.x;
            float h3 = acc[mt][nt][3] * third + bv.y;
            if (rowa < V) {
                *reinterpret_cast<float2*>(hout + (size_t)rowa * DD + col) =
                    make_float2(h0, h1);
                ssum[nt * 2 + 0] += h0; ssq[nt * 2 + 0] += h0 * h0;
                ssum[nt * 2 + 1] += h1; ssq[nt * 2 + 1] += h1 * h1;
            }
            if (rowb < V) {
                *reinterpret_cast<float2*>(hout + (size_t)rowb * DD + col) =
                    make_float2(h2, h3);
                ssum[nt * 2 + 0] += h2; ssq[nt * 2 + 0] += h2 * h2;
                ssum[nt * 2 + 1] += h3; ssq[nt * 2 + 1] += h3 * h3;
            }
        }
    }
#pragma unroll
    for (int i = 0; i < 16; i++) {
#pragma unroll
        for (int off = 4; off <= 16; off <<= 1) {
            ssum[i] += __shfl_xor_sync(0xFFFFFFFFu, ssum[i], off);
            ssq[i]  += __shfl_xor_sync(0xFFFFFFFFu, ssq[i],  off);
        }
    }
    __syncthreads();
    float* Ssum = reinterpret_cast<float*>(sm);
    float* Ssq  = reinterpret_cast<float*>(sm + 4096);
#pragma unroll
    for (int j = 0; j < 4; j++) { Ssum[tid + j * 256] = 0.f; Ssq[tid + j * 256] = 0.f; }
    __syncthreads();
    if (lane < 4) {
#pragma unroll
        for (int nt = 0; nt < 8; nt++) {
            int col = wn * 64 + nt * 8 + lane * 2;
            Ssum[wid * 128 + col]     = ssum[nt * 2 + 0];
            Ssum[wid * 128 + col + 1] = ssum[nt * 2 + 1];
            Ssq [wid * 128 + col]     = ssq[nt * 2 + 0];
            Ssq [wid * 128 + col + 1] = ssq[nt * 2 + 1];
        }
    }
    __syncthreads();
    if (tid < 128) {
        float a = 0.f, b = 0.f;
#pragma unroll
        for (int w = 0; w < 8; w++) { a += Ssum[w * 128 + tid]; b += Ssq[w * 128 + tid]; }
        atomicAdd(&g_stats[tid],       a);
        atomicAdd(&g_stats[128 + tid], b);
    }
}

// ---------------------------------------------------------------------------
// BatchNorm + ReLU, in place on h
// ---------------------------------------------------------------------------
__global__ void bn_kernel(float* __restrict__ h, int V) {
    __shared__ float ms[128];
    __shared__ float rs[128];
    if (threadIdx.x < 128) {
        float invn = 1.f / (float)V;
        float s  = g_stats[threadIdx.x];
        float sq = g_stats[128 + threadIdx.x];
        float m  = s * invn;
        float var = sq * invn - m * m;
        ms[threadIdx.x] = m;
        rs[threadIdx.x] = rsqrtf(var + 1e-5f);
    }
    __syncthreads();
    size_t total = (size_t)V * 32;
    float4* h4 = reinterpret_cast<float4*>(h);
    for (size_t i = (size_t)blockIdx.x * blockDim.x + threadIdx.x; i < total;
         i += (size_t)gridDim.x * blockDim.x) {
        int c4 = (int)(i & 31) * 4;
        float4 hv = h4[i];
        hv.x = fmaxf((hv.x - ms[c4 + 0]) * rs[c4 + 0], 0.f);
        hv.y = fmaxf((hv.y - ms[c4 + 1]) * rs[c4 + 1], 0.f);
        hv.z = fmaxf((hv.z - ms[c4 + 2]) * rs[c4 + 2], 0.f);
        hv.w = fmaxf((hv.w - ms[c4 + 3]) * rs[c4 + 3], 0.f);
        h4[i] = hv;
    }
}

// ---------------------------------------------------------------------------
// rel_repr @ w_rel, 4 rel rows per block
// ---------------------------------------------------------------------------
__global__ void relw_kernel(const float* __restrict__ rel,
                            const float* __restrict__ w_rel,
                            float* __restrict__ out, int R) {
    __shared__ float rr[4][128];
    int r0 = blockIdx.x * 4;
    int c = threadIdx.x;
#pragma unroll
    for (int j = 0; j < 4; j++)
        rr[j][c] = (r0 + j < R) ? rel[(size_t)(r0 + j) * DD + c] : 0.f;
    __syncthreads();
    float a0 = 0.f, a1 = 0.f, a2 = 0.f, a3 = 0.f;
#pragma unroll 4
    for (int k = 0; k < 128; k++) {
        float w = __ldg(&w_rel[(size_t)k * DD + c]);
        a0 += rr[0][k] * w;
        a1 += rr[1][k] * w;
        a2 += rr[2][k] * w;
        a3 += rr[3][k] * w;
    }
    if (r0 + 0 < R) out[(size_t)(r0 + 0) * DD + c] = a0;
    if (r0 + 1 < R) out[(size_t)(r0 + 1) * DD + c] = a1;
    if (r0 + 2 < R) out[(size_t)(r0 + 2) * DD + c] = a2;
    if (r0 + 3 < R) out[(size_t)(r0 + 3) * DD + c] = a3;
}

// ---------------------------------------------------------------------------
extern "C" void kernel_launch(void* const* d_in, const int* in_sizes, int n_in,
                              void* d_out, int out_size) {
    const float* x        = (const float*)d_in[0];
    const float* rel      = (const float*)d_in[1];
    const float* enorm    = (const float*)d_in[2];
    const float* in_w     = (const float*)d_in[3];
    const float* out_w    = (const float*)d_in[4];
    const float* loop_w   = (const float*)d_in[5];
    const float* w_rel    = (const float*)d_in[6];
    const float* loop_rel = (const float*)d_in[7];
    const float* bias     = (const float*)d_in[8];
    const int*   src      = (const int*)d_in[9];
    const int*   dst      = (const int*)d_in[10];
    const int*   et       = (const int*)d_in[11];

    int V = in_sizes[0] / DD;
    int R = in_sizes[1] / DD;
    int E = in_sizes[2];
    int half = E / 2;
    int N = 2 * V;
    int NB = (N + 1023) / 1024;

    float* h    = (float*)d_out;
    float* out2 = h + (size_t)V * DD;

    void* dptr = nullptr; void* sptr = nullptr;
    cudaGetSymbolAddress(&dptr, g_deg);
    cudaGetSymbolAddress(&sptr, g_stats);
    cudaMemsetAsync(dptr, 0, (size_t)N * sizeof(int), 0);
    cudaMemsetAsync(sptr, 0, 2 * DD * sizeof(float), 0);

    cudaFuncSetAttribute(gemm_mma, cudaFuncAttributeMaxDynamicSharedMemorySize,
                         SMEM_GEMM);

    prep_w<<<6, 256>>>(in_w, out_w, loop_w, loop_rel);
    hist_kernel<<<(E + 255) / 256, 256>>>(dst, E, half, V);
    scan1_kernel<<<NB, 256>>>(N);
    scan2_kernel<<<1, 256>>>(NB, N);
    scan3_kernel<<<NB, 256>>>(N);
    fill_kernel<<<(E + 255) / 256, 256>>>(dst, E, half, V);
    gather_kernel<<<(N + 7) / 8, 256>>>(x, rel, enorm, src, et, N);
    gemm_mma<<<(V + 127) / 128, 256, SMEM_GEMM>>>(x, bias, h, V);
    bn_kernel<<<1024, 256>>>(h, V);
    relw_kernel<<<(R + 3) / 4, 128>>>(rel, w_rel, out2, R);
}

// round 16
// speedup vs baseline: 2.7595x; 1.2585x over previous
#include <cuda_runtime.h>
#include <cuda_fp16.h>
#include <cstdint>
#include <cstddef>

#define DD 128
#define VMAX 100000

// ---------------------------------------------------------------------------
// Global scratch (no allocs allowed)
// ---------------------------------------------------------------------------
__device__ float g_Y[2u * VMAX * DD];                    // Y_in | Y_out, fp32
__device__ float g_stats[2 * DD];                        // BN sum / sumsq
// W image: 6 chunks (in k0,k1 | out k0,k1 | loop' k0,k1), each [128 n][64 k] fp16
__device__ __align__(16) unsigned char g_Bh[6 * 16384];

// ---------------------------------------------------------------------------
// PTX helpers (generic-target safe: ldmatrix + mma.sync + cp.async)
// ---------------------------------------------------------------------------
__device__ __forceinline__ uint32_t smem_u32(const void* p) {
    uint32_t a;
    asm("{ .reg .u64 t; cvta.to.shared.u64 t, %1; cvt.u32.u64 %0, t; }" : "=r"(a) : "l"(p));
    return a;
}

#define LDSM4(r, addr)                                                          \
    asm volatile("ldmatrix.sync.aligned.m8n8.x4.shared.b16 {%0,%1,%2,%3}, [%4];" \
        : "=r"((r)[0]), "=r"((r)[1]), "=r"((r)[2]), "=r"((r)[3]) : "r"(addr))

#define MMA16816F16(d, a, b0, b1)                                               \
    asm volatile("mma.sync.aligned.m16n8k16.row.col.f32.f16.f16.f32 "           \
        "{%0,%1,%2,%3}, {%4,%5,%6,%7}, {%8,%9}, {%0,%1,%2,%3};"                 \
        : "+f"((d)[0]), "+f"((d)[1]), "+f"((d)[2]), "+f"((d)[3])                \
        : "r"((a)[0]), "r"((a)[1]), "r"((a)[2]), "r"((a)[3]), "r"(b0), "r"(b1))

#define CP_ASYNC16(saddr, gptr)                                                 \
    asm volatile("cp.async.cg.shared.global [%0], [%1], 16;"                    \
        :: "r"(saddr), "l"(gptr) : "memory")
#define CP_COMMIT()  asm volatile("cp.async.commit_group;" ::: "memory")
#define CP_WAIT0()   asm volatile("cp.async.wait_group 0;" ::: "memory")

// fp16 convert (round-to-nearest) of 4 floats -> 2x uint32 (h2 pairs)
__device__ __forceinline__ uint2 cvt4h(const float4 z) {
    __half2 h01 = __floats2half2_rn(z.x, z.y);
    __half2 h23 = __floats2half2_rn(z.z, z.w);
    uint2 r;
    r.x = *reinterpret_cast<uint32_t*>(&h01);
    r.y = *reinterpret_cast<uint32_t*>(&h23);
    return r;
}

// ---------------------------------------------------------------------------
// Kernel 0: W image, fp16, 6 chunks of [128 n][64 k]. loop_rel folded in.
// ---------------------------------------------------------------------------
__global__ void prep_w(const float* __restrict__ in_w, const float* __restrict__ out_w,
                       const float* __restrict__ loop_w,
                       const float* __restrict__ loop_rel) {
    int c = blockIdx.x;
    const float* W = (c < 2) ? in_w : (c < 4 ? out_w : loop_w);
    int k0 = (c & 1) * 64;
    __half* bh = reinterpret_cast<__half*>(g_Bh + c * 16384);
    for (int i = threadIdx.x; i < 8192; i += blockDim.x) {
        int n = i >> 6, k = i & 63;
        float v = W[(size_t)(k0 + k) * DD + n];
        if (c >= 4) v *= loop_rel[k0 + k];   // exact fold: (x*lr)@W = x@(diag(lr)W)
        bh[n * 64 + k] = __float2half_rn(v);
    }
}

// ---------------------------------------------------------------------------
// Kernel 1: per-edge scatter for ONE direction.  yb[dst] += norm*(x[src]*rel[et])
// ---------------------------------------------------------------------------
__global__ void edge_kernel(const float* __restrict__ x,
                            const float* __restrict__ rel,
                            const float* __restrict__ enorm,
                            const int* __restrict__ src,
                            const int* __restrict__ dst,
                            const int* __restrict__ et,
                            int n_edges,
                            float* __restrict__ yb) {
    int e = (blockIdx.x * blockDim.x + threadIdx.x) >> 5;
    if (e >= n_edges) return;
    int lane = threadIdx.x & 31;

    int   s = __ldg(&src[e]);
    int   d = __ldg(&dst[e]);
    int   t = __ldg(&et[e]);
    float n = __ldg(&enorm[e]);

    float4 xv = __ldg(reinterpret_cast<const float4*>(x)   + (size_t)s * 32 + lane);
    float4 rv = __ldg(reinterpret_cast<const float4*>(rel) + (size_t)t * 32 + lane);

    float a = n * xv.x * rv.x;
    float b = n * xv.y * rv.y;
    float c = n * xv.z * rv.z;
    float w = n * xv.w * rv.w;

    float* yp = yb + (size_t)d * DD + lane * 4;
    asm volatile("red.global.add.v4.f32 [%0], {%1,%2,%3,%4};"
                 :: "l"(yp), "f"(a), "f"(b), "f"(c), "f"(w) : "memory");
}

// ---------------------------------------------------------------------------
// Kernel 2: mma.sync fp16 single-pass GEMM (A -> fp16 rn, B fp16).
//   h[v,:] = ( [Yin | Yout | x][v,:384] @ [in_w; out_w; diag(lr)loop_w] )/3 + bias
// CTA tile 128x128, 8 warps (warp tile 32x64), K-chunks of 64 (6 iterations).
// smem: Ah[0:18432) Bh[18432:36864), rows of 144 B.
// ---------------------------------------------------------------------------
#define ROWB 144
#define OAH 0
#define OBH 18432
#define SMEM_GEMM 36864

__global__ void __launch_bounds__(256, 2) gemm_mma(
    const float* __restrict__ x,
    const float* __restrict__ bias,
    float* __restrict__ hout,
    int V) {

    extern __shared__ __align__(16) unsigned char sm[];
    const uint32_t sb = smem_u32(sm);
    const uint32_t uAh = sb + OAH;
    const uint32_t uBh = sb + OBH;

    const int tid  = threadIdx.x;
    const int wid  = tid >> 5;
    const int lane = tid & 31;
    const int wm   = wid & 3;    // 4 warps over M (32 rows each)
    const int wn   = wid >> 2;   // 2 warps over N (64 cols each)
    const int m0   = blockIdx.x * 128;

    float acc[2][8][4];
#pragma unroll
    for (int i = 0; i < 2; i++)
#pragma unroll
        for (int j = 0; j < 8; j++)
#pragma unroll
            for (int k = 0; k < 4; k++) acc[i][j][k] = 0.f;

    for (int c = 0; c < 6; c++) {
        __syncthreads();
        // ---- B chunk via cp.async (16 KB) ----
        {
            const unsigned char* gh = g_Bh + c * 16384;
#pragma unroll
            for (int j = 0; j < 4; j++) {
                int i = tid + j * 256;          // 0..1023 16B pieces
                int r = i >> 3, g = i & 7;
                CP_ASYNC16(uBh + r * ROWB + g * 16, gh + r * 128 + g * 16);
            }
            CP_COMMIT();
        }
        // ---- load + fp16-convert A chunk: 128 rows x 64 k fp32 ----
        {
            const int k0 = (c & 1) * 64;
            const float* Ab = (c < 2) ? g_Y : (c < 4 ? g_Y + (size_t)V * DD : x);
#pragma unroll
            for (int j = 0; j < 8; j++) {
                int i = tid + j * 256;          // 0..2047 float4 slots
                int r = i >> 4, g = i & 15;
                int v = m0 + r;
                float4 z = make_float4(0.f, 0.f, 0.f, 0.f);
                if (v < V)
                    z = *reinterpret_cast<const float4*>(Ab + (size_t)v * DD + k0 + g * 4);
                uint2 hv = cvt4h(z);
                *reinterpret_cast<uint2*>(sm + OAH + r * ROWB + g * 8) = hv;
            }
        }
        CP_WAIT0();
        __syncthreads();

        // ---- mma over 4 k16 steps, single pass ----
#pragma unroll
        for (int k16 = 0; k16 < 4; k16++) {
            const uint32_t kb = k16 * 32 + ((lane >> 4) << 4);
            const uint32_t arow = (uint32_t)(wm * 32 + (lane & 15)) * ROWB + kb;
            const uint32_t brow = (uint32_t)(wn * 64 + (lane & 15)) * ROWB + kb;

            uint32_t ah[2][4], bb[4][4];
#pragma unroll
            for (int mt = 0; mt < 2; mt++) LDSM4(ah[mt], uAh + arow + mt * 16 * ROWB);
#pragma unroll
            for (int nb = 0; nb < 4; nb++) LDSM4(bb[nb], uBh + brow + nb * 16 * ROWB);
#pragma unroll
            for (int mt = 0; mt < 2; mt++)
#pragma unroll
                for (int nb = 0; nb < 4; nb++) {
                    MMA16816F16(acc[mt][nb * 2 + 0], ah[mt], bb[nb][0], bb[nb][2]);
                    MMA16816F16(acc[mt][nb * 2 + 1], ah[mt], bb[nb][1], bb[nb][3]);
                }
        }
    }

    // ---- epilogue: /3 + bias, store h, accumulate BN stats ----
    const float third = 1.f / 3.f;
    float ssum[16], ssq[16];
#pragma unroll
    for (int i = 0; i < 16; i++) { ssum[i] = 0.f; ssq[i] = 0.f; }

#pragma unroll
    for (int mt = 0; mt < 2; mt++) {
        int rowa = m0 + wm * 32 + mt * 16 + (lane >> 2);
        int rowb = rowa + 8;
#pragma unroll
        for (int nt = 0; nt < 8; nt++) {
            int col = wn * 64 + nt * 8 + (lane & 3) * 2;
            float2 bv = *reinterpret_cast<const float2*>(bias + col);
            float h0 = acc[mt][nt][0] * third + bv.x;
            float h1 = acc[mt][nt][1] * third + bv.y;
            float h2 = acc[mt][nt][2] * third + bv.x;
            float h3 = acc[mt][nt][3] * third + bv.y;
            if (rowa < V) {
                *reinterpret_cast<float2*>(hout + (size_t)rowa * DD + col) =
                    make_float2(h0, h1);
                ssum[nt * 2 + 0] += h0; ssq[nt * 2 + 0] += h0 * h0;
                ssum[nt * 2 + 1] += h1; ssq[nt * 2 + 1] += h1 * h1;
            }
            if (rowb < V) {
                *reinterpret_cast<float2*>(hout + (size_t)rowb * DD + col) =
                    make_float2(h2, h3);
                ssum[nt * 2 + 0] += h2; ssq[nt * 2 + 0] += h2 * h2;
                ssum[nt * 2 + 1] += h3; ssq[nt * 2 + 1] += h3 * h3;
            }
        }
    }
    // reduce over lane bits 2..4 (rows within warp)
#pragma unroll
    for (int i = 0; i < 16; i++) {
#pragma unroll
        for (int off = 4; off <= 16; off <<= 1) {
            ssum[i] += __shfl_xor_sync(0xFFFFFFFFu, ssum[i], off);
            ssq[i]  += __shfl_xor_sync(0xFFFFFFFFu, ssq[i],  off);
        }
    }
    __syncthreads();  // smem reuse
    float* Ssum = reinterpret_cast<float*>(sm);          // [8][128]
    float* Ssq  = reinterpret_cast<float*>(sm + 4096);   // [8][128]
#pragma unroll
    for (int j = 0; j < 4; j++) { Ssum[tid + j * 256] = 0.f; Ssq[tid + j * 256] = 0.f; }
    __syncthreads();
    if (lane < 4) {
#pragma unroll
        for (int nt = 0; nt < 8; nt++) {
            int col = wn * 64 + nt * 8 + lane * 2;
            Ssum[wid * 128 + col]     = ssum[nt * 2 + 0];
            Ssum[wid * 128 + col + 1] = ssum[nt * 2 + 1];
            Ssq [wid * 128 + col]     = ssq[nt * 2 + 0];
            Ssq [wid * 128 + col + 1] = ssq[nt * 2 + 1];
        }
    }
    __syncthreads();
    if (tid < 128) {
        float a = 0.f, b = 0.f;
#pragma unroll
        for (int w = 0; w < 8; w++) { a += Ssum[w * 128 + tid]; b += Ssq[w * 128 + tid]; }
        atomicAdd(&g_stats[tid],       a);
        atomicAdd(&g_stats[128 + tid], b);
    }
}

// ---------------------------------------------------------------------------
// Kernel 3: BatchNorm + ReLU, in place on h
// ---------------------------------------------------------------------------
__global__ void bn_kernel(float* __restrict__ h, int V) {
    __shared__ float ms[128];
    __shared__ float rs[128];
    if (threadIdx.x < 128) {
        float invn = 1.f / (float)V;
        float s  = g_stats[threadIdx.x];
        float sq = g_stats[128 + threadIdx.x];
        float m  = s * invn;
        float var = sq * invn - m * m;
        ms[threadIdx.x] = m;
        rs[threadIdx.x] = rsqrtf(var + 1e-5f);
    }
    __syncthreads();
    size_t total = (size_t)V * 32;
    float4* h4 = reinterpret_cast<float4*>(h);
    for (size_t i = (size_t)blockIdx.x * blockDim.x + threadIdx.x; i < total;
         i += (size_t)gridDim.x * blockDim.x) {
        int c4 = (int)(i & 31) * 4;
        float4 hv = h4[i];
        hv.x = fmaxf((hv.x - ms[c4 + 0]) * rs[c4 + 0], 0.f);
        hv.y = fmaxf((hv.y - ms[c4 + 1]) * rs[c4 + 1], 0.f);
        hv.z = fmaxf((hv.z - ms[c4 + 2]) * rs[c4 + 2], 0.f);
        hv.w = fmaxf((hv.w - ms[c4 + 3]) * rs[c4 + 3], 0.f);
        h4[i] = hv;
    }
}

// ---------------------------------------------------------------------------
// Kernel 4: rel_repr @ w_rel, 4 rel rows per block
// ---------------------------------------------------------------------------
__global__ void relw_kernel(const float* __restrict__ rel,
                            const float* __restrict__ w_rel,
                            float* __restrict__ out, int R) {
    __shared__ float rr[4][128];
    int r0 = blockIdx.x * 4;
    int c = threadIdx.x;
#pragma unroll
    for (int j = 0; j < 4; j++)
        rr[j][c] = (r0 + j < R) ? rel[(size_t)(r0 + j) * DD + c] : 0.f;
    __syncthreads();
    float a0 = 0.f, a1 = 0.f, a2 = 0.f, a3 = 0.f;
#pragma unroll 4
    for (int k = 0; k < 128; k++) {
        float w = __ldg(&w_rel[(size_t)k * DD + c]);
        a0 += rr[0][k] * w;
        a1 += rr[1][k] * w;
        a2 += rr[2][k] * w;
        a3 += rr[3][k] * w;
    }
    if (r0 + 0 < R) out[(size_t)(r0 + 0) * DD + c] = a0;
    if (r0 + 1 < R) out[(size_t)(r0 + 1) * DD + c] = a1;
    if (r0 + 2 < R) out[(size_t)(r0 + 2) * DD + c] = a2;
    if (r0 + 3 < R) out[(size_t)(r0 + 3) * DD + c] = a3;
}

// ---------------------------------------------------------------------------
extern "C" void kernel_launch(void* const* d_in, const int* in_sizes, int n_in,
                              void* d_out, int out_size) {
    const float* x        = (const float*)d_in[0];
    const float* rel      = (const float*)d_in[1];
    const float* enorm    = (const float*)d_in[2];
    const float* in_w     = (const float*)d_in[3];
    const float* out_w    = (const float*)d_in[4];
    const float* loop_w   = (const float*)d_in[5];
    const float* w_rel    = (const float*)d_in[6];
    const float* loop_rel = (const float*)d_in[7];
    const float* bias     = (const float*)d_in[8];
    const int*   src      = (const int*)d_in[9];
    const int*   dst      = (const int*)d_in[10];
    const int*   et       = (const int*)d_in[11];

    int V = in_sizes[0] / DD;
    int R = in_sizes[1] / DD;
    int E = in_sizes[2];
    int half = E / 2;

    float* h    = (float*)d_out;
    float* out2 = h + (size_t)V * DD;

    void* yptr = nullptr; void* sptr = nullptr;
    cudaGetSymbolAddress(&yptr, g_Y);
    cudaGetSymbolAddress(&sptr, g_stats);
    float* Yin  = (float*)yptr;
    float* Yout = Yin + (size_t)V * DD;
    cudaMemsetAsync(yptr, 0, (size_t)2 * V * DD * sizeof(float), 0);
    cudaMemsetAsync(sptr, 0, 2 * DD * sizeof(float), 0);

    cudaFuncSetAttribute(gemm_mma, cudaFuncAttributeMaxDynamicSharedMemorySize,
                         SMEM_GEMM);

    prep_w<<<6, 256>>>(in_w, out_w, loop_w, loop_rel);
    // two passes: per-launch working set (x + half of Y) fits in L2
    edge_kernel<<<(half + 7) / 8, 256>>>(x, rel, enorm, src, dst, et, half, Yin);
    edge_kernel<<<(E - half + 7) / 8, 256>>>(x, rel, enorm + half, src + half,
                                             dst + half, et + half, E - half, Yout);
    gemm_mma<<<(V + 127) / 128, 256, SMEM_GEMM>>>(x, bias, h, V);
    bn_kernel<<<1024, 256>>>(h, V);
    relw_kernel<<<(R + 3) / 4, 128>>>(rel, w_rel, out2, R);
}

// round 17
// speedup vs baseline: 3.1362x; 1.1365x over previous
#include <cuda_runtime.h>
#include <cuda_fp16.h>
#include <cstdint>
#include <cstddef>

#define DD 128
#define VMAX 100000

// ---------------------------------------------------------------------------
// Global scratch (no allocs allowed)
// ---------------------------------------------------------------------------
__device__ __align__(16) __half g_Yh[2u * VMAX * DD];    // Y_in | Y_out, fp16
__device__ float g_stats[2 * DD];                        // BN sum / sumsq
// W image: 6 chunks (in k0,k1 | out k0,k1 | loop' k0,k1), each [128 n][64 k] fp16
__device__ __align__(16) unsigned char g_Bh[6 * 16384];

// ---------------------------------------------------------------------------
// PTX helpers (generic-target safe: ldmatrix + mma.sync + cp.async + red.f16x2)
// ---------------------------------------------------------------------------
__device__ __forceinline__ uint32_t smem_u32(const void* p) {
    uint32_t a;
    asm("{ .reg .u64 t; cvta.to.shared.u64 t, %1; cvt.u32.u64 %0, t; }" : "=r"(a) : "l"(p));
    return a;
}

#define LDSM4(r, addr)                                                          \
    asm volatile("ldmatrix.sync.aligned.m8n8.x4.shared.b16 {%0,%1,%2,%3}, [%4];" \
        : "=r"((r)[0]), "=r"((r)[1]), "=r"((r)[2]), "=r"((r)[3]) : "r"(addr))

#define MMA16816F16(d, a, b0, b1)                                               \
    asm volatile("mma.sync.aligned.m16n8k16.row.col.f32.f16.f16.f32 "           \
        "{%0,%1,%2,%3}, {%4,%5,%6,%7}, {%8,%9}, {%0,%1,%2,%3};"                 \
        : "+f"((d)[0]), "+f"((d)[1]), "+f"((d)[2]), "+f"((d)[3])                \
        : "r"((a)[0]), "r"((a)[1]), "r"((a)[2]), "r"((a)[3]), "r"(b0), "r"(b1))

#define CP_ASYNC16(saddr, gptr)                                                 \
    asm volatile("cp.async.cg.shared.global [%0], [%1], 16;"                    \
        :: "r"(saddr), "l"(gptr) : "memory")
#define CP_ASYNC16Z(saddr, gptr, sz)                                            \
    asm volatile("cp.async.cg.shared.global [%0], [%1], 16, %2;"                \
        :: "r"(saddr), "l"(gptr), "r"(sz) : "memory")
#define CP_COMMIT()  asm volatile("cp.async.commit_group;" ::: "memory")
#define CP_WAIT0()   asm volatile("cp.async.wait_group 0;" ::: "memory")

#define RED_F16X2(ptr, val)                                                     \
    asm volatile("red.global.add.noftz.f16x2 [%0], %1;"                         \
        :: "l"(ptr), "r"(val) : "memory")

// fp16 convert (round-to-nearest) of 4 floats -> 2x uint32 (h2 pairs)
__device__ __forceinline__ uint2 cvt4h(const float4 z) {
    __half2 h01 = __floats2half2_rn(z.x, z.y);
    __half2 h23 = __floats2half2_rn(z.z, z.w);
    uint2 r;
    r.x = *reinterpret_cast<uint32_t*>(&h01);
    r.y = *reinterpret_cast<uint32_t*>(&h23);
    return r;
}

// ---------------------------------------------------------------------------
// Kernel 0: W image, fp16, 6 chunks of [128 n][64 k]. loop_rel folded in.
// ---------------------------------------------------------------------------
__global__ void prep_w(const float* __restrict__ in_w, const float* __restrict__ out_w,
                       const float* __restrict__ loop_w,
                       const float* __restrict__ loop_rel) {
    int c = blockIdx.x;
    const float* W = (c < 2) ? in_w : (c < 4 ? out_w : loop_w);
    int k0 = (c & 1) * 64;
    __half* bh = reinterpret_cast<__half*>(g_Bh + c * 16384);
    for (int i = threadIdx.x; i < 8192; i += blockDim.x) {
        int n = i >> 6, k = i & 63;
        float v = W[(size_t)(k0 + k) * DD + n];
        if (c >= 4) v *= loop_rel[k0 + k];   // exact fold: (x*lr)@W = x@(diag(lr)W)
        bh[n * 64 + k] = __float2half_rn(v);
    }
}

// ---------------------------------------------------------------------------
// Kernel 1: per-edge scatter for ONE direction, fp16 atomics.
//   yb[dst] += fp16( norm * (x[src] * rel[et]) )
// ---------------------------------------------------------------------------
__global__ void edge_kernel(const float* __restrict__ x,
                            const float* __restrict__ rel,
                            const float* __restrict__ enorm,
                            const int* __restrict__ src,
                            const int* __restrict__ dst,
                            const int* __restrict__ et,
                            int n_edges,
                            __half* __restrict__ yb) {
    int e = (blockIdx.x * blockDim.x + threadIdx.x) >> 5;
    if (e >= n_edges) return;
    int lane = threadIdx.x & 31;

    int   s = __ldg(&src[e]);
    int   d = __ldg(&dst[e]);
    int   t = __ldg(&et[e]);
    float n = __ldg(&enorm[e]);

    float4 xv = __ldg(reinterpret_cast<const float4*>(x)   + (size_t)s * 32 + lane);
    float4 rv = __ldg(reinterpret_cast<const float4*>(rel) + (size_t)t * 32 + lane);

    __half2 p0 = __floats2half2_rn(n * xv.x * rv.x, n * xv.y * rv.y);
    __half2 p1 = __floats2half2_rn(n * xv.z * rv.z, n * xv.w * rv.w);
    uint32_t u0 = *reinterpret_cast<uint32_t*>(&p0);
    uint32_t u1 = *reinterpret_cast<uint32_t*>(&p1);

    __half* yp = yb + (size_t)d * DD + lane * 4;
    RED_F16X2(yp,     u0);
    RED_F16X2(yp + 2, u1);
}

// ---------------------------------------------------------------------------
// Kernel 2: mma.sync fp16 single-pass GEMM.
//   h[v,:] = ( [Yin | Yout | x][v,:384] @ [in_w; out_w; diag(lr)loop_w] )/3 + bias
// Chunks 0-3: A rows are ALREADY fp16 (g_Yh) -> pure cp.async, no cvt.
// Chunks 4-5: x fp32 -> cvt path.
// CTA tile 128x128, 8 warps (warp tile 32x64), K-chunks of 64 (6 iterations).
// smem: Ah[0:18432) Bh[18432:36864), rows of 144 B.
// ---------------------------------------------------------------------------
#define ROWB 144
#define OAH 0
#define OBH 18432
#define SMEM_GEMM 36864

__global__ void __launch_bounds__(256, 2) gemm_mma(
    const float* __restrict__ x,
    const float* __restrict__ bias,
    float* __restrict__ hout,
    int V) {

    extern __shared__ __align__(16) unsigned char sm[];
    const uint32_t sb = smem_u32(sm);
    const uint32_t uAh = sb + OAH;
    const uint32_t uBh = sb + OBH;

    const int tid  = threadIdx.x;
    const int wid  = tid >> 5;
    const int lane = tid & 31;
    const int wm   = wid & 3;    // 4 warps over M (32 rows each)
    const int wn   = wid >> 2;   // 2 warps over N (64 cols each)
    const int m0   = blockIdx.x * 128;

    float acc[2][8][4];
#pragma unroll
    for (int i = 0; i < 2; i++)
#pragma unroll
        for (int j = 0; j < 8; j++)
#pragma unroll
            for (int k = 0; k < 4; k++) acc[i][j][k] = 0.f;

    for (int c = 0; c < 6; c++) {
        __syncthreads();
        // ---- B chunk via cp.async (16 KB) ----
        {
            const unsigned char* gh = g_Bh + c * 16384;
#pragma unroll
            for (int j = 0; j < 4; j++) {
                int i = tid + j * 256;          // 0..1023 16B pieces
                int r = i >> 3, g = i & 7;
                CP_ASYNC16(uBh + r * ROWB + g * 16, gh + r * 128 + g * 16);
            }
        }
        // ---- A chunk ----
        if (c < 4) {
            // fp16 Y rows: direct cp.async, zero-fill beyond V
            const __half* Ab = g_Yh + (c < 2 ? 0 : (size_t)V * DD);
            const int k0 = (c & 1) * 64;
#pragma unroll
            for (int j = 0; j < 4; j++) {
                int i = tid + j * 256;          // 0..1023 16B pieces
                int r = i >> 3, g = i & 7;
                int v = m0 + r;
                uint32_t sz = (v < V) ? 16u : 0u;
                const unsigned char* srcp = reinterpret_cast<const unsigned char*>(
                    Ab + (size_t)(v < V ? v : 0) * DD + k0) + g * 16;
                CP_ASYNC16Z(uAh + r * ROWB + g * 16, srcp, sz);
            }
            CP_COMMIT();
        } else {
            CP_COMMIT();
            // x fp32 -> fp16 cvt path
            const int k0 = (c & 1) * 64;
#pragma unroll
            for (int j = 0; j < 8; j++) {
                int i = tid + j * 256;          // 0..2047 float4 slots
                int r = i >> 4, g = i & 15;
                int v = m0 + r;
                float4 z = make_float4(0.f, 0.f, 0.f, 0.f);
                if (v < V)
                    z = *reinterpret_cast<const float4*>(x + (size_t)v * DD + k0 + g * 4);
                uint2 hv = cvt4h(z);
                *reinterpret_cast<uint2*>(sm + OAH + r * ROWB + g * 8) = hv;
            }
        }
        CP_WAIT0();
        __syncthreads();

        // ---- mma over 4 k16 steps, single pass ----
#pragma unroll
        for (int k16 = 0; k16 < 4; k16++) {
            const uint32_t kb = k16 * 32 + ((lane >> 4) << 4);
            const uint32_t arow = (uint32_t)(wm * 32 + (lane & 15)) * ROWB + kb;
            const uint32_t brow = (uint32_t)(wn * 64 + (lane & 15)) * ROWB + kb;

            uint32_t ah[2][4], bb[4][4];
#pragma unroll
            for (int mt = 0; mt < 2; mt++) LDSM4(ah[mt], uAh + arow + mt * 16 * ROWB);
#pragma unroll
            for (int nb = 0; nb < 4; nb++) LDSM4(bb[nb], uBh + brow + nb * 16 * ROWB);
#pragma unroll
            for (int mt = 0; mt < 2; mt++)
#pragma unroll
                for (int nb = 0; nb < 4; nb++) {
                    MMA16816F16(acc[mt][nb * 2 + 0], ah[mt], bb[nb][0], bb[nb][2]);
                    MMA16816F16(acc[mt][nb * 2 + 1], ah[mt], bb[nb][1], bb[nb][3]);
                }
        }
    }

    // ---- epilogue: /3 + bias, store h, accumulate BN stats ----
    const float third = 1.f / 3.f;
    float ssum[16], ssq[16];
#pragma unroll
    for (int i = 0; i < 16; i++) { ssum[i] = 0.f; ssq[i] = 0.f; }

#pragma unroll
    for (int mt = 0; mt < 2; mt++) {
        int rowa = m0 + wm * 32 + mt * 16 + (lane >> 2);
        int rowb = rowa + 8;
#pragma unroll
        for (int nt = 0; nt < 8; nt++) {
            int col = wn * 64 + nt * 8 + (lane & 3) * 2;
            float2 bv = *reinterpret_cast<const float2*>(bias + col);
            float h0 = acc[mt][nt][0] * third + bv.x;
            float h1 = acc[mt][nt][1] * third + bv.y;
            float h2 = acc[mt][nt][2] * third + bv.x;
            float h3 = acc[mt][nt][3] * third + bv.y;
            if (rowa < V) {
                *reinterpret_cast<float2*>(hout + (size_t)rowa * DD + col) =
                    make_float2(h0, h1);
                ssum[nt * 2 + 0] += h0; ssq[nt * 2 + 0] += h0 * h0;
                ssum[nt * 2 + 1] += h1; ssq[nt * 2 + 1] += h1 * h1;
            }
            if (rowb < V) {
                *reinterpret_cast<float2*>(hout + (size_t)rowb * DD + col) =
                    make_float2(h2, h3);
                ssum[nt * 2 + 0] += h2; ssq[nt * 2 + 0] += h2 * h2;
                ssum[nt * 2 + 1] += h3; ssq[nt * 2 + 1] += h3 * h3;
            }
        }
    }
    // reduce over lane bits 2..4 (rows within warp)
#pragma unroll
    for (int i = 0; i < 16; i++) {
#pragma unroll
        for (int off = 4; off <= 16; off <<= 1) {
            ssum[i] += __shfl_xor_sync(0xFFFFFFFFu, ssum[i], off);
            ssq[i]  += __shfl_xor_sync(0xFFFFFFFFu, ssq[i],  off);
        }
    }
    __syncthreads();  // smem reuse
    float* Ssum = reinterpret_cast<float*>(sm);          // [8][128]
    float* Ssq  = reinterpret_cast<float*>(sm + 4096);   // [8][128]
#pragma unroll
    for (int j = 0; j < 4; j++) { Ssum[tid + j * 256] = 0.f; Ssq[tid + j * 256] = 0.f; }
    __syncthreads();
    if (lane < 4) {
#pragma unroll
        for (int nt = 0; nt < 8; nt++) {
            int col = wn * 64 + nt * 8 + lane * 2;
            Ssum[wid * 128 + col]     = ssum[nt * 2 + 0];
            Ssum[wid * 128 + col + 1] = ssum[nt * 2 + 1];
            Ssq [wid * 128 + col]     = ssq[nt * 2 + 0];
            Ssq [wid * 128 + col + 1] = ssq[nt * 2 + 1];
        }
    }
    __syncthreads();
    if (tid < 128) {
        float a = 0.f, b = 0.f;
#pragma unroll
        for (int w = 0; w < 8; w++) { a += Ssum[w * 128 + tid]; b += Ssq[w * 128 + tid]; }
        atomicAdd(&g_stats[tid],       a);
        atomicAdd(&g_stats[128 + tid], b);
    }
}

// ---------------------------------------------------------------------------
// Kernel 3: BatchNorm + ReLU, in place on h
// ---------------------------------------------------------------------------
__global__ void bn_kernel(float* __restrict__ h, int V) {
    __shared__ float ms[128];
    __shared__ float rs[128];
    if (threadIdx.x < 128) {
        float invn = 1.f / (float)V;
        float s  = g_stats[threadIdx.x];
        float sq = g_stats[128 + threadIdx.x];
        float m  = s * invn;
        float var = sq * invn - m * m;
        ms[threadIdx.x] = m;
        rs[threadIdx.x] = rsqrtf(var + 1e-5f);
    }
    __syncthreads();
    size_t total = (size_t)V * 32;
    float4* h4 = reinterpret_cast<float4*>(h);
    for (size_t i = (size_t)blockIdx.x * blockDim.x + threadIdx.x; i < total;
         i += (size_t)gridDim.x * blockDim.x) {
        int c4 = (int)(i & 31) * 4;
        float4 hv = h4[i];
        hv.x = fmaxf((hv.x - ms[c4 + 0]) * rs[c4 + 0], 0.f);
        hv.y = fmaxf((hv.y - ms[c4 + 1]) * rs[c4 + 1], 0.f);
        hv.z = fmaxf((hv.z - ms[c4 + 2]) * rs[c4 + 2], 0.f);
        hv.w = fmaxf((hv.w - ms[c4 + 3]) * rs[c4 + 3], 0.f);
        h4[i] = hv;
    }
}

// ---------------------------------------------------------------------------
// Kernel 4: rel_repr @ w_rel, 4 rel rows per block
// ---------------------------------------------------------------------------
__global__ void relw_kernel(const float* __restrict__ rel,
                            const float* __restrict__ w_rel,
                            float* __restrict__ out, int R) {
    __shared__ float rr[4][128];
    int r0 = blockIdx.x * 4;
    int c = threadIdx.x;
#pragma unroll
    for (int j = 0; j < 4; j++)
        rr[j][c] = (r0 + j < R) ? rel[(size_t)(r0 + j) * DD + c] : 0.f;
    __syncthreads();
    float a0 = 0.f, a1 = 0.f, a2 = 0.f, a3 = 0.f;
#pragma unroll 4
    for (int k = 0; k < 128; k++) {
        float w = __ldg(&w_rel[(size_t)k * DD + c]);
        a0 += rr[0][k] * w;
        a1 += rr[1][k] * w;
        a2 += rr[2][k] * w;
        a3 += rr[3][k] * w;
    }
    if (r0 + 0 < R) out[(size_t)(r0 + 0) * DD + c] = a0;
    if (r0 + 1 < R) out[(size_t)(r0 + 1) * DD + c] = a1;
    if (r0 + 2 < R) out[(size_t)(r0 + 2) * DD + c] = a2;
    if (r0 + 3 < R) out[(size_t)(r0 + 3) * DD + c] = a3;
}

// ---------------------------------------------------------------------------
extern "C" void kernel_launch(void* const* d_in, const int* in_sizes, int n_in,
                              void* d_out, int out_size) {
    const float* x        = (const float*)d_in[0];
    const float* rel      = (const float*)d_in[1];
    const float* enorm    = (const float*)d_in[2];
    const float* in_w     = (const float*)d_in[3];
    const float* out_w    = (const float*)d_in[4];
    const float* loop_w   = (const float*)d_in[5];
    const float* w_rel    = (const float*)d_in[6];
    const float* loop_rel = (const float*)d_in[7];
    const float* bias     = (const float*)d_in[8];
    const int*   src      = (const int*)d_in[9];
    const int*   dst      = (const int*)d_in[10];
    const int*   et       = (const int*)d_in[11];

    int V = in_sizes[0] / DD;
    int R = in_sizes[1] / DD;
    int E = in_sizes[2];
    int half = E / 2;

    float* h    = (float*)d_out;
    float* out2 = h + (size_t)V * DD;

    void* yptr = nullptr; void* sptr = nullptr;
    cudaGetSymbolAddress(&yptr, g_Yh);
    cudaGetSymbolAddress(&sptr, g_stats);
    __half* Yin  = (__half*)yptr;
    __half* Yout = Yin + (size_t)V * DD;
    cudaMemsetAsync(yptr, 0, (size_t)2 * V * DD * sizeof(__half), 0);
    cudaMemsetAsync(sptr, 0, 2 * DD * sizeof(float), 0);

    cudaFuncSetAttribute(gemm_mma, cudaFuncAttributeMaxDynamicSharedMemorySize,
                         SMEM_GEMM);

    prep_w<<<6, 256>>>(in_w, out_w, loop_w, loop_rel);
    // two passes: per-launch working set (x + half of Y) stays L2-resident
    edge_kernel<<<(half + 7) / 8, 256>>>(x, rel, enorm, src, dst, et, half, Yin);
    edge_kernel<<<(E - half + 7) / 8, 256>>>(x, rel, enorm + half, src + half,
                                             dst + half, et + half, E - half, Yout);
    gemm_mma<<<(V + 127) / 128, 256, SMEM_GEMM>>>(x, bias, h, V);
    bn_kernel<<<2048, 256>>>(h, V);
    relw_kernel<<<(R + 3) / 4, 128>>>(rel, w_rel, out2, R);
}